// round 13
// baseline (speedup 1.0000x reference)
#include <cuda_runtime.h>
#include <cuda_fp16.h>
#include <cstdint>

// Problem constants
#define NL    4
#define HD    1024
#define KK2   2048
#define NJC   2048      // interleaved output cols (even=forcing, odd=tau)
#define MM    8192
#define MAXT  50
#define DTC   0.05f
#define EPS_TAU  1e-6f
#define EPS_CONV 1e-3f

#define STAGE_BYTES 32768              // A 16KB + B 16KB per stage (fp16, k-chunk 64)
#define SMEM_BYTES  (2 * STAGE_BYTES)  // mainloop stages
#define SMEM_TOTAL  (SMEM_BYTES + 64)  // + reduction/flag scratch
#define NCTA        296                // 2 x 148 — co-resident on both B300/GB300
#define TILES_PER_PHASE 1024           // 64 row-blocks x 16 j-blocks
#define TILES_PER_STEP  (NL * TILES_PER_PHASE)
#define TOTAL_TICKETS   (MAXT * TILES_PER_STEP)

// ---------------- device scratch (static: no allocation allowed) ------------
__device__ __half g_W[(size_t)NL * NJC * KK2];   // packed fp16 weights [l][j][k]
__device__ float  g_bias[NL * NJC];              // interleaved biases
__device__ __half g_xh[(size_t)MM * HD];         // fp16 input x
__device__ float  g_stA[(size_t)NL * MM * HD];   // exact states ping
__device__ float  g_stB[(size_t)NL * MM * HD];   // exact states pong
__device__ __half g_shA[(size_t)NL * MM * HD];   // fp16 states ping
__device__ __half g_shB[(size_t)NL * MM * HD];   // fp16 states pong
// dependency tracking
__device__ int      g_rowdone[MAXT * NL * 64];   // per (phase, row-block) tile count
__device__ int      g_stepdone[MAXT];            // tiles finished in step t
__device__ int      g_stepres[MAXT];             // step t fully resolved (conv decided)
__device__ unsigned g_maxd_arr[MAXT];            // per-step max |delta| (float bits)
__device__ int      g_done;
__device__ int      g_tconv;
__device__ int      g_outsel;                    // answer buffer parity

// ---------------- PTX helpers ----------------
__device__ __forceinline__ unsigned sptr(const void* p) {
    return (unsigned)__cvta_generic_to_shared(p);
}
__device__ __forceinline__ void cpasync16(unsigned dst, const void* src) {
    asm volatile("cp.async.cg.shared.global [%0], [%1], 16;\n" :: "r"(dst), "l"(src));
}
__device__ __forceinline__ void cpcommit() { asm volatile("cp.async.commit_group;\n"); }
template<int N> __device__ __forceinline__ void cpwait() {
    asm volatile("cp.async.wait_group %0;\n" :: "n"(N));
}
__device__ __forceinline__ void ldsm4(unsigned& r0, unsigned& r1, unsigned& r2, unsigned& r3,
                                      unsigned addr) {
    asm volatile("ldmatrix.sync.aligned.m8n8.x4.shared.b16 {%0,%1,%2,%3}, [%4];\n"
                 : "=r"(r0), "=r"(r1), "=r"(r2), "=r"(r3) : "r"(addr));
}
__device__ __forceinline__ void mma_f16(float* c, const unsigned* a, const unsigned* b) {
    asm volatile(
        "mma.sync.aligned.m16n8k16.row.col.f32.f16.f16.f32 "
        "{%0,%1,%2,%3}, {%4,%5,%6,%7}, {%8,%9}, {%0,%1,%2,%3};\n"
        : "+f"(c[0]), "+f"(c[1]), "+f"(c[2]), "+f"(c[3])
        : "r"(a[0]), "r"(a[1]), "r"(a[2]), "r"(a[3]), "r"(b[0]), "r"(b[1]));
}
__device__ __forceinline__ int ldacq(const int* p) {
    int v;
    asm volatile("ld.acquire.gpu.b32 %0, [%1];" : "=r"(v) : "l"(p));
    return v;
}
__device__ __forceinline__ void strel(int* p, int v) {
    asm volatile("st.release.gpu.b32 [%0], %1;" :: "l"(p), "r"(v));
}
// Accurate tanh independent of fast-math substitutions
__device__ __forceinline__ float my_tanh(float x) {
    float ax = fabsf(x);
    float e  = __expf(-2.0f * ax);
    float r  = (1.0f - e) / (1.0f + e);
    return copysignf(r, x);
}

// ---------------- pack / init kernels ----------------
__global__ void pack_w_kernel(const float* __restrict__ ws, const float* __restrict__ wi,
                              const float* __restrict__ wt) {
    const size_t total = (size_t)NL * NJC * KK2;
    for (size_t idx = (size_t)blockIdx.x * blockDim.x + threadIdx.x; idx < total;
         idx += (size_t)gridDim.x * blockDim.x) {
        int k = (int)(idx & (KK2 - 1));
        size_t r = idx >> 11;
        int j = (int)(r & (NJC - 1));
        int l = (int)(r >> 11);
        int n = j >> 1;
        float v;
        if (j & 1) v = wt[((size_t)(l * HD + n)) * (2 * HD) + k];
        else       v = (k < HD) ? wi[((size_t)(l * HD + n)) * HD + k]
                                : ws[((size_t)(l * HD + n)) * HD + (k - HD)];
        g_W[idx] = __float2half_rn(v);
    }
}

__global__ void pack_bias_kernel(const float* __restrict__ bs, const float* __restrict__ bi,
                                 const float* __restrict__ bt) {
    int idx = blockIdx.x * blockDim.x + threadIdx.x;
    if (idx < NL * NJC) {
        int j = idx & (NJC - 1);
        int l = idx >> 11;
        int n = j >> 1;
        g_bias[idx] = (j & 1) ? bt[l * HD + n] : (bs[l * HD + n] + bi[l * HD + n]);
    }
}

__global__ void pack_x_kernel(const float* __restrict__ x) {
    const size_t n = (size_t)MM * HD;
    for (size_t i = (size_t)blockIdx.x * blockDim.x + threadIdx.x; i < n;
         i += (size_t)gridDim.x * blockDim.x)
        g_xh[i] = __float2half_rn(x[i]);
}

__global__ void init_states_kernel() {
    const size_t n4 = ((size_t)NL * MM * HD) / 4;
    float4* pa = (float4*)g_stA;
    uint2*  ph = (uint2*)g_shA;
    float4 z = make_float4(0.f, 0.f, 0.f, 0.f);
    uint2  zh = make_uint2(0u, 0u);
    size_t gtid = (size_t)blockIdx.x * blockDim.x + threadIdx.x;
    for (size_t i = gtid; i < n4; i += (size_t)gridDim.x * blockDim.x) {
        pa[i] = z; ph[i] = zh;
    }
    // zero dependency state (every graph replay must reset!)
    for (size_t i = gtid; i < MAXT * NL * 64; i += (size_t)gridDim.x * blockDim.x)
        g_rowdone[i] = 0;
    if (gtid < MAXT) { g_stepdone[gtid] = 0; g_stepres[gtid] = 0; g_maxd_arr[gtid] = 0u; }
    if (gtid == 0) { g_done = 0; g_tconv = MAXT; g_outsel = 0; }
}

// ---------------- persistent fused kernel ------------------------------------
// 296 co-resident CTAs, static round-robin over 50x4x1024 tickets.
// Per tile: the R11-champion 128x128 fp16-MMA GEMM + liquid-time epilogue.
__global__ void __launch_bounds__(256, 2) persist_kernel(
    const __half* __restrict__ xh,
    const __half* __restrict__ shA, const __half* __restrict__ shB,
    const float*  __restrict__ stA, const float*  __restrict__ stB,
    const __half* __restrict__ Wall, const float* __restrict__ ball) {
    const int tid   = threadIdx.x;
    const int lane  = tid & 31;
    const int wid   = tid >> 5;
    const int warpM = wid & 1;
    const int warpJ = wid >> 1;
    const int g8    = lane >> 2, tc = lane & 3;
    const size_t MMHD = (size_t)MM * HD;

    extern __shared__ char smem[];   // [stage0 32K][stage1 32K][sred 32B][flag]
    const unsigned smemB = sptr(smem);
    float* sred  = (float*)(smem + SMEM_BYTES);
    int*   sflag = (int*)(smem + SMEM_BYTES + 32);

    const int qr = tid >> 3;   // 0..31
    const int qg = tid & 7;    // 16B group (8 halfs) within a 128B row

    for (int g = blockIdx.x; g < TOTAL_TICKETS; g += NCTA) {
        const int tile  = g & (TILES_PER_PHASE - 1);
        const int phase = g >> 10;
        const int l     = phase & 3;
        const int t     = phase >> 2;
        const int rb    = tile >> 4;
        const int jb    = tile & 15;
        const int row0  = rb * 128;
        const int j0    = jb * 128;
        const int nb    = jb * 64 + warpJ * 16;

        // ---- dependency waits (tid0), then CTA-uniform skip flag ----
        if (tid == 0) {
            if (t >= 2)  while (ldacq(&g_stepres[t - 2]) == 0) __nanosleep(64);
            if (t > 0)   while (ldacq(&g_rowdone[((t - 1) * 4 + l) * 64 + rb]) < 16) __nanosleep(64);
            if (l > 0)   while (ldacq(&g_rowdone[(t * 4 + l - 1) * 64 + rb]) < 16) __nanosleep(64);
            int dn = *(volatile int*)&g_done;
            *sflag = (dn && t > *(volatile int*)&g_tconv) ? 1 : 0;
        }
        __syncthreads();
        const bool skip = (*sflag != 0);
        float mval = 0.f;   // tid0's reduced max-delta for this tile

        if (!skip) {
            const int pin = t & 1;
            const __half* hinH  = (pin ? shB : shA) + (size_t)l * MMHD;
            const float*  hinE  = (pin ? stB : stA) + (size_t)l * MMHD;
            float*        houtE = (float*)((pin ? stA : stB) + (size_t)l * MMHD);
            __half*       houtH = (__half*)((pin ? shA : shB) + (size_t)l * MMHD);
            const __half* curH  = (l == 0) ? xh
                                 : (pin ? shA : shB) + (size_t)(l - 1) * MMHD;
            const __half* W    = Wall + (size_t)l * NJC * KK2;
            const float*  bias = ball + l * NJC;

            // L2-prefetch epilogue's exact-state tile
            {
                const float* pp = hinE + (size_t)(row0 + (tid >> 1)) * HD
                                       + jb * 64 + (tid & 1) * 32;
                asm volatile("prefetch.global.L2 [%0];" :: "l"(pp));
            }

            float acc[4][4][4];
            #pragma unroll
            for (int a = 0; a < 4; ++a)
                #pragma unroll
                for (int b = 0; b < 4; ++b)
                    #pragma unroll
                    for (int c = 0; c < 4; ++c) acc[a][b][c] = 0.f;

            auto load_stage = [&](int kk, int st) {
                const __half* abase = (kk < HD) ? (curH + kk) : (hinH + (kk - HD));
                const __half* bbase = W + kk;
                unsigned aS = smemB + (unsigned)st * STAGE_BYTES;
                unsigned bS = aS + 16384u;
                #pragma unroll
                for (int i = 0; i < 4; ++i) {
                    int r = i * 32 + qr;
                    unsigned sw = (unsigned)((r * 8 + (qg ^ (r & 7))) << 4);
                    cpasync16(aS + sw, abase + (size_t)(row0 + r) * HD + qg * 8);
                    cpasync16(bS + sw, bbase + (size_t)(j0 + r) * KK2 + qg * 8);
                }
            };

            load_stage(0, 0);
            cpcommit();

            for (int kt = 0; kt < 32; ++kt) {
                if (kt + 1 < 32) { load_stage((kt + 1) * 64, (kt + 1) & 1); cpcommit(); cpwait<1>(); }
                else             { cpwait<0>(); }
                __syncthreads();
                unsigned aB = smemB + (unsigned)(kt & 1) * STAGE_BYTES;
                unsigned bB = aB + 16384u;

                #pragma unroll
                for (int ks = 0; ks < 4; ++ks) {
                    unsigned afr[4][4];
                    #pragma unroll
                    for (int mt = 0; mt < 4; ++mt) {
                        int row = warpM * 64 + mt * 16 + ((lane >> 3) & 1) * 8 + (lane & 7);
                        int grp = ks * 2 + ((lane >> 4) & 1);
                        unsigned ad = aB + (unsigned)((row * 8 + (grp ^ (row & 7))) << 4);
                        ldsm4(afr[mt][0], afr[mt][1], afr[mt][2], afr[mt][3], ad);
                    }
                    unsigned bfr[4][2];
                    #pragma unroll
                    for (int p = 0; p < 2; ++p) {
                        int jrow = warpJ * 32 + p * 16 + ((lane >> 4) & 1) * 8 + (lane & 7);
                        int grp  = ks * 2 + ((lane >> 3) & 1);
                        unsigned ad = bB + (unsigned)((jrow * 8 + (grp ^ (jrow & 7))) << 4);
                        ldsm4(bfr[p * 2][0], bfr[p * 2][1], bfr[p * 2 + 1][0], bfr[p * 2 + 1][1], ad);
                    }
                    #pragma unroll
                    for (int mt = 0; mt < 4; ++mt)
                        #pragma unroll
                        for (int nt = 0; nt < 4; ++nt)
                            mma_f16(acc[mt][nt], afr[mt], bfr[nt]);
                }
                __syncthreads();
            }

            // ---- epilogue: liquid-time state update ----
            float dmax = 0.f;
            const int rbase = row0 + warpM * 64;
            #pragma unroll
            for (int mt = 0; mt < 4; ++mt) {
                #pragma unroll
                for (int nt = 0; nt < 4; ++nt) {
                    int n = nb + nt * 4 + tc;
                    float2 bb = ((const float2*)bias)[n];   // .x forcing, .y tau
                    int r0r = rbase + mt * 16 + g8;
                    #pragma unroll
                    for (int hh = 0; hh < 2; ++hh) {
                        int r = r0r + hh * 8;
                        float pf = acc[mt][nt][hh * 2 + 0] + bb.x;
                        float pt = acc[mt][nt][hh * 2 + 1] + bb.y;
                        float h   = hinE[(size_t)r * HD + n];
                        float f   = my_tanh(pf);
                        float tau = 0.5f * (my_tanh(0.5f * pt) + 1.0f);   // stable sigmoid
                        float hn  = h + DTC * (f - h / (tau + EPS_TAU));
                        hn = fminf(10.0f, fmaxf(-10.0f, hn));
                        houtE[(size_t)r * HD + n] = hn;
                        houtH[(size_t)r * HD + n] = __float2half_rn(hn);
                        dmax = fmaxf(dmax, fabsf(hn - h));
                    }
                }
            }
            #pragma unroll
            for (int o = 16; o > 0; o >>= 1)
                dmax = fmaxf(dmax, __shfl_xor_sync(0xffffffffu, dmax, o));
            if (lane == 0) sred[wid] = dmax;
        }

        __syncthreads();   // all writes done (or skip); sred valid
        if (tid == 0) {
            if (!skip) {
                float m = sred[0];
                #pragma unroll
                for (int i = 1; i < 8; ++i) m = fmaxf(m, sred[i]);
                mval = m;
                atomicMax(&g_maxd_arr[t], __float_as_uint(mval));
            }
            __threadfence();   // publish epilogue stores + dmax before counters
            atomicAdd(&g_rowdone[(t * 4 + l) * 64 + rb], 1);
            int sd = atomicAdd(&g_stepdone[t], 1);
            if (sd == TILES_PER_STEP - 1) {
                // resolver: serialize behind previous step's resolution
                if (t > 0) while (ldacq(&g_stepres[t - 1]) == 0) __nanosleep(64);
                if (!g_done && __uint_as_float(g_maxd_arr[t]) < EPS_CONV) {
                    g_done = 1; g_tconv = t; g_outsel = (t + 1) & 1;
                }
                __threadfence();
                strel(&g_stepres[t], 1);
            }
        }
        // no barrier needed here: next iteration's sflag write + B1 protect smem
    }
}

__global__ void finalize_kernel(float* __restrict__ out, int out_size) {
    const float* base = (g_outsel == 0) ? g_stA : g_stB;
    const float* src  = base + (size_t)3 * MM * HD;   // layer 3
    const size_t n = (size_t)MM * HD;
    for (size_t i = (size_t)blockIdx.x * blockDim.x + threadIdx.x; i < n;
         i += (size_t)gridDim.x * blockDim.x)
        out[i] = src[i];
    if (blockIdx.x == 0 && threadIdx.x == 0 && (size_t)out_size > n)
        out[n] = (float)g_tconv;
}

// ---------------- host orchestration (graph-capturable) ----------------------
extern "C" void kernel_launch(void* const* d_in, const int* in_sizes, int n_in,
                              void* d_out, int out_size) {
    const float* x  = (const float*)d_in[0];
    const float* ws = (const float*)d_in[1];
    const float* bs = (const float*)d_in[2];
    const float* wi = (const float*)d_in[3];
    const float* bi = (const float*)d_in[4];
    const float* wt = (const float*)d_in[5];
    const float* bt = (const float*)d_in[6];
    (void)in_sizes; (void)n_in;

    cudaFuncSetAttribute(persist_kernel,
                         cudaFuncAttributeMaxDynamicSharedMemorySize, SMEM_TOTAL);

    float *stA, *stB, *bp;
    __half *shA, *shB, *xh, *Wp;
    cudaGetSymbolAddress((void**)&stA, g_stA);
    cudaGetSymbolAddress((void**)&stB, g_stB);
    cudaGetSymbolAddress((void**)&shA, g_shA);
    cudaGetSymbolAddress((void**)&shB, g_shB);
    cudaGetSymbolAddress((void**)&xh,  g_xh);
    cudaGetSymbolAddress((void**)&Wp,  g_W);
    cudaGetSymbolAddress((void**)&bp,  g_bias);

    pack_w_kernel<<<4096, 256>>>(ws, wi, wt);
    pack_bias_kernel<<<32, 256>>>(bs, bi, bt);
    pack_x_kernel<<<2048, 256>>>(x);
    init_states_kernel<<<512, 256>>>();

    persist_kernel<<<NCTA, 256, SMEM_TOTAL>>>(xh, shA, shB, stA, stB, Wp, bp);

    finalize_kernel<<<2048, 256>>>((float*)d_out, out_size);
}

// round 14
// speedup vs baseline: 1.1278x; 1.1278x over previous
#include <cuda_runtime.h>
#include <cuda_fp16.h>
#include <cstdint>

// Problem constants
#define NL    4
#define HD    1024
#define KK2   2048
#define NJC   2048      // interleaved output cols (even=forcing, odd=tau)
#define MM    8192
#define MAXT  50
#define DTC   0.05f
#define EPS_TAU  1e-6f
#define EPS_CONV 1e-3f

#define STAGE_BYTES 32768          // A 16KB + B 16KB per stage (fp16, k-chunk 64)
#define SMEM_BYTES  (2 * STAGE_BYTES)

// ---------------- device scratch (static: no allocation allowed) ------------
__device__ __half g_W[(size_t)NL * NJC * KK2];   // packed fp16 weights [l][j][k]
__device__ float  g_bias[NL * NJC];              // interleaved biases
__device__ __half g_xh[(size_t)MM * HD];         // fp16 input x
__device__ float  g_stA[(size_t)NL * MM * HD];   // exact states ping
__device__ float  g_stB[(size_t)NL * MM * HD];   // exact states pong
__device__ __half g_shA[(size_t)NL * MM * HD];   // fp16 states ping
__device__ __half g_shB[(size_t)NL * MM * HD];   // fp16 states pong
// Layer-0 constant partial sums (x-half of the combined GEMM), stored in
// per-thread fragment layout: tile (rb*16+jb) -> 4096 float4s, [q*256 + tid].
__device__ float  g_P0[(size_t)MM * NJC];
__device__ int      g_done;
__device__ int      g_tconv;
__device__ unsigned g_maxd;

// ---------------- PTX helpers ----------------
__device__ __forceinline__ unsigned sptr(const void* p) {
    return (unsigned)__cvta_generic_to_shared(p);
}
__device__ __forceinline__ void cpasync16(unsigned dst, const void* src) {
    asm volatile("cp.async.cg.shared.global [%0], [%1], 16;\n" :: "r"(dst), "l"(src));
}
__device__ __forceinline__ void cpcommit() { asm volatile("cp.async.commit_group;\n"); }
template<int N> __device__ __forceinline__ void cpwait() {
    asm volatile("cp.async.wait_group %0;\n" :: "n"(N));
}
__device__ __forceinline__ void ldsm4(unsigned& r0, unsigned& r1, unsigned& r2, unsigned& r3,
                                      unsigned addr) {
    asm volatile("ldmatrix.sync.aligned.m8n8.x4.shared.b16 {%0,%1,%2,%3}, [%4];\n"
                 : "=r"(r0), "=r"(r1), "=r"(r2), "=r"(r3) : "r"(addr));
}
__device__ __forceinline__ void mma_f16(float* c, const unsigned* a, const unsigned* b) {
    asm volatile(
        "mma.sync.aligned.m16n8k16.row.col.f32.f16.f16.f32 "
        "{%0,%1,%2,%3}, {%4,%5,%6,%7}, {%8,%9}, {%0,%1,%2,%3};\n"
        : "+f"(c[0]), "+f"(c[1]), "+f"(c[2]), "+f"(c[3])
        : "r"(a[0]), "r"(a[1]), "r"(a[2]), "r"(a[3]), "r"(b[0]), "r"(b[1]));
}
// Accurate tanh independent of fast-math substitutions
__device__ __forceinline__ float my_tanh(float x) {
    float ax = fabsf(x);
    float e  = __expf(-2.0f * ax);
    float r  = (1.0f - e) / (1.0f + e);
    return copysignf(r, x);
}

// ---------------- pack / init kernels ----------------
__global__ void pack_w_kernel(const float* __restrict__ ws, const float* __restrict__ wi,
                              const float* __restrict__ wt) {
    const size_t total = (size_t)NL * NJC * KK2;
    for (size_t idx = (size_t)blockIdx.x * blockDim.x + threadIdx.x; idx < total;
         idx += (size_t)gridDim.x * blockDim.x) {
        int k = (int)(idx & (KK2 - 1));
        size_t r = idx >> 11;
        int j = (int)(r & (NJC - 1));
        int l = (int)(r >> 11);
        int n = j >> 1;
        float v;
        if (j & 1) v = wt[((size_t)(l * HD + n)) * (2 * HD) + k];
        else       v = (k < HD) ? wi[((size_t)(l * HD + n)) * HD + k]
                                : ws[((size_t)(l * HD + n)) * HD + (k - HD)];
        g_W[idx] = __float2half_rn(v);
    }
}

__global__ void pack_bias_kernel(const float* __restrict__ bs, const float* __restrict__ bi,
                                 const float* __restrict__ bt) {
    int idx = blockIdx.x * blockDim.x + threadIdx.x;
    if (idx < NL * NJC) {
        int j = idx & (NJC - 1);
        int l = idx >> 11;
        int n = j >> 1;
        g_bias[idx] = (j & 1) ? bt[l * HD + n] : (bs[l * HD + n] + bi[l * HD + n]);
    }
}

__global__ void pack_x_kernel(const float* __restrict__ x) {
    const size_t n = (size_t)MM * HD;
    for (size_t i = (size_t)blockIdx.x * blockDim.x + threadIdx.x; i < n;
         i += (size_t)gridDim.x * blockDim.x)
        g_xh[i] = __float2half_rn(x[i]);
}

__global__ void init_states_kernel() {
    const size_t n4 = ((size_t)NL * MM * HD) / 4;
    float4* pa = (float4*)g_stA;
    uint2*  ph = (uint2*)g_shA;
    float4 z = make_float4(0.f, 0.f, 0.f, 0.f);
    uint2  zh = make_uint2(0u, 0u);
    for (size_t i = (size_t)blockIdx.x * blockDim.x + threadIdx.x; i < n4;
         i += (size_t)gridDim.x * blockDim.x) { pa[i] = z; ph[i] = zh; }
    if (blockIdx.x == 0 && threadIdx.x == 0) { g_done = 0; g_tconv = MAXT; g_maxd = 0u; }
}

// ---------------- shared GEMM mainloop (templated) ---------------------------
// NKT k-tiles of 64, A rows from (curH for k<HD, hinH else) offset by KOFF.
template<int NKT, int KOFF>
__device__ __forceinline__ void gemm_tiles(
    float acc[4][4][4], const __half* curH, const __half* hinH,
    const __half* W, int row0, int j0, unsigned smemB,
    int tid, int lane, int warpM, int warpJ) {
    const int qr = tid >> 3;
    const int qg = tid & 7;

    auto load_stage = [&](int kt, int st) {
        int kk = KOFF + kt * 64;
        const __half* abase = (kk < HD) ? (curH + kk) : (hinH + (kk - HD));
        const __half* bbase = W + kk;
        unsigned aS = smemB + (unsigned)st * STAGE_BYTES;
        unsigned bS = aS + 16384u;
        #pragma unroll
        for (int i = 0; i < 4; ++i) {
            int r = i * 32 + qr;
            unsigned sw = (unsigned)((r * 8 + (qg ^ (r & 7))) << 4);
            cpasync16(aS + sw, abase + (size_t)(row0 + r) * HD + qg * 8);
            cpasync16(bS + sw, bbase + (size_t)(j0 + r) * KK2 + qg * 8);
        }
    };

    load_stage(0, 0);
    cpcommit();

    for (int kt = 0; kt < NKT; ++kt) {
        if (kt + 1 < NKT) { load_stage(kt + 1, (kt + 1) & 1); cpcommit(); cpwait<1>(); }
        else              { cpwait<0>(); }
        __syncthreads();
        unsigned aB = smemB + (unsigned)(kt & 1) * STAGE_BYTES;
        unsigned bB = aB + 16384u;

        #pragma unroll
        for (int ks = 0; ks < 4; ++ks) {
            unsigned afr[4][4];
            #pragma unroll
            for (int mt = 0; mt < 4; ++mt) {
                int row = warpM * 64 + mt * 16 + ((lane >> 3) & 1) * 8 + (lane & 7);
                int grp = ks * 2 + ((lane >> 4) & 1);
                unsigned ad = aB + (unsigned)((row * 8 + (grp ^ (row & 7))) << 4);
                ldsm4(afr[mt][0], afr[mt][1], afr[mt][2], afr[mt][3], ad);
            }
            unsigned bfr[4][2];
            #pragma unroll
            for (int p = 0; p < 2; ++p) {
                int jrow = warpJ * 32 + p * 16 + ((lane >> 4) & 1) * 8 + (lane & 7);
                int grp  = ks * 2 + ((lane >> 3) & 1);
                unsigned ad = bB + (unsigned)((jrow * 8 + (grp ^ (jrow & 7))) << 4);
                ldsm4(bfr[p * 2][0], bfr[p * 2][1], bfr[p * 2 + 1][0], bfr[p * 2 + 1][1], ad);
            }
            #pragma unroll
            for (int mt = 0; mt < 4; ++mt)
                #pragma unroll
                for (int nt = 0; nt < 4; ++nt)
                    mma_f16(acc[mt][nt], afr[mt], bfr[nt]);
        }
        __syncthreads();
    }
}

// ---------------- layer-0 constant-part precompute ---------------------------
// P0 = x-half GEMM (k 0..1023) for layer 0, written in fragment layout.
__global__ void __launch_bounds__(256, 2) precompute_p0_kernel(
    const __half* __restrict__ xh, const __half* __restrict__ W0) {
    const int tid   = threadIdx.x;
    const int lane  = tid & 31;
    const int wid   = tid >> 5;
    const int warpM = wid & 1;
    const int warpJ = wid >> 1;
    const int row0  = blockIdx.y * 128;
    const int j0    = blockIdx.x * 128;

    extern __shared__ char smem[];
    const unsigned smemB = sptr(smem);

    float acc[4][4][4];
    #pragma unroll
    for (int a = 0; a < 4; ++a)
        #pragma unroll
        for (int b = 0; b < 4; ++b)
            #pragma unroll
            for (int c = 0; c < 4; ++c) acc[a][b][c] = 0.f;

    gemm_tiles<16, 0>(acc, xh, xh, W0, row0, j0, smemB, tid, lane, warpM, warpJ);

    float4* blob = (float4*)g_P0 + (size_t)(blockIdx.y * 16 + blockIdx.x) * 4096;
    #pragma unroll
    for (int mt = 0; mt < 4; ++mt)
        #pragma unroll
        for (int nt = 0; nt < 4; ++nt)
            blob[(mt * 4 + nt) * 256 + tid] =
                make_float4(acc[mt][nt][0], acc[mt][nt][1], acc[mt][nt][2], acc[mt][nt][3]);
}

// ---------------- fused fp16-MMA GEMM + state-update kernel ------------------
// L0=true: acc initialized from g_P0, only the h-half (k 1024..2047) is computed.
template<bool L0>
__global__ void __launch_bounds__(256, 2) step_layer_kernel(
    const __half* __restrict__ curH, const __half* __restrict__ hinH,
    const float* __restrict__ hinE, float* __restrict__ houtE,
    __half* __restrict__ houtH, const __half* __restrict__ W,
    const float* __restrict__ bias) {
    const int tid   = threadIdx.x;
    const int lane  = tid & 31;
    const int wid   = tid >> 5;
    const int warpM = wid & 1;
    const int warpJ = wid >> 1;
    const int row0  = blockIdx.y * 128;
    const int j0    = blockIdx.x * 128;
    const int nb    = blockIdx.x * 64 + warpJ * 16;
    const int g8    = lane >> 2, tc = lane & 3;

    // Frozen after convergence: propagate exact states only.
    if (*(volatile int*)&g_done) {
        int r   = row0 + (tid >> 1);
        int nb2 = blockIdx.x * 64 + (tid & 1) * 32;
        const float4* s4 = (const float4*)(hinE  + (size_t)r * HD + nb2);
        float4*       d4 = (float4*)(houtE + (size_t)r * HD + nb2);
        #pragma unroll
        for (int i = 0; i < 8; ++i) d4[i] = s4[i];
        return;
    }

    // L2-prefetch the epilogue's exact-state tile.
    {
        const float* pp = hinE + (size_t)(row0 + (tid >> 1)) * HD
                               + blockIdx.x * 64 + (tid & 1) * 32;
        asm volatile("prefetch.global.L2 [%0];" :: "l"(pp));
    }

    extern __shared__ char smem[];
    const unsigned smemB = sptr(smem);

    float acc[4][4][4];
    if (L0) {
        const float4* blob = (const float4*)g_P0
                           + (size_t)(blockIdx.y * 16 + blockIdx.x) * 4096;
        #pragma unroll
        for (int mt = 0; mt < 4; ++mt)
            #pragma unroll
            for (int nt = 0; nt < 4; ++nt) {
                float4 v = blob[(mt * 4 + nt) * 256 + tid];
                acc[mt][nt][0] = v.x; acc[mt][nt][1] = v.y;
                acc[mt][nt][2] = v.z; acc[mt][nt][3] = v.w;
            }
    } else {
        #pragma unroll
        for (int a = 0; a < 4; ++a)
            #pragma unroll
            for (int b = 0; b < 4; ++b)
                #pragma unroll
                for (int c = 0; c < 4; ++c) acc[a][b][c] = 0.f;
    }

    if (L0) gemm_tiles<16, HD>(acc, curH, hinH, W, row0, j0, smemB, tid, lane, warpM, warpJ);
    else    gemm_tiles<32, 0>(acc, curH, hinH, W, row0, j0, smemB, tid, lane, warpM, warpJ);

    // ---- epilogue: liquid-time state update on thread-local (f,tau) pairs ----
    float dmax = 0.f;
    const int rb = row0 + warpM * 64;
    #pragma unroll
    for (int mt = 0; mt < 4; ++mt) {
        #pragma unroll
        for (int nt = 0; nt < 4; ++nt) {
            int n = nb + nt * 4 + tc;
            float2 bb = ((const float2*)bias)[n];   // .x forcing, .y tau
            int r0r = rb + mt * 16 + g8;
            #pragma unroll
            for (int hh = 0; hh < 2; ++hh) {
                int r = r0r + hh * 8;
                float pf = acc[mt][nt][hh * 2 + 0] + bb.x;
                float pt = acc[mt][nt][hh * 2 + 1] + bb.y;
                float h   = hinE[(size_t)r * HD + n];
                float f   = my_tanh(pf);
                float tau = 0.5f * (my_tanh(0.5f * pt) + 1.0f);   // stable sigmoid
                float hn  = h + DTC * (f - h / (tau + EPS_TAU));
                hn = fminf(10.0f, fmaxf(-10.0f, hn));
                houtE[(size_t)r * HD + n] = hn;
                houtH[(size_t)r * HD + n] = __float2half_rn(hn);
                dmax = fmaxf(dmax, fabsf(hn - h));
            }
        }
    }

    #pragma unroll
    for (int o = 16; o > 0; o >>= 1)
        dmax = fmaxf(dmax, __shfl_xor_sync(0xffffffffu, dmax, o));
    float* sred = (float*)smem;
    if (lane == 0) sred[wid] = dmax;
    __syncthreads();
    if (tid == 0) {
        float m = sred[0];
        #pragma unroll
        for (int i = 1; i < 8; ++i) m = fmaxf(m, sred[i]);
        atomicMax(&g_maxd, __float_as_uint(m));
    }
}

__global__ void conv_check_kernel(int t) {
    if (!g_done && __uint_as_float(g_maxd) < EPS_CONV) { g_done = 1; g_tconv = t; }
    g_maxd = 0u;
}

__global__ void finalize_kernel(float* __restrict__ out, int out_size) {
    const float* src = g_stA + (size_t)3 * MM * HD;   // layer 3, final parity = A
    const size_t n = (size_t)MM * HD;
    for (size_t i = (size_t)blockIdx.x * blockDim.x + threadIdx.x; i < n;
         i += (size_t)gridDim.x * blockDim.x)
        out[i] = src[i];
    if (blockIdx.x == 0 && threadIdx.x == 0 && (size_t)out_size > n)
        out[n] = (float)g_tconv;
}

// ---------------- host orchestration (graph-capturable) ----------------------
extern "C" void kernel_launch(void* const* d_in, const int* in_sizes, int n_in,
                              void* d_out, int out_size) {
    const float* x  = (const float*)d_in[0];
    const float* ws = (const float*)d_in[1];
    const float* bs = (const float*)d_in[2];
    const float* wi = (const float*)d_in[3];
    const float* bi = (const float*)d_in[4];
    const float* wt = (const float*)d_in[5];
    const float* bt = (const float*)d_in[6];
    (void)in_sizes; (void)n_in;

    cudaFuncSetAttribute(step_layer_kernel<true>,
                         cudaFuncAttributeMaxDynamicSharedMemorySize, SMEM_BYTES);
    cudaFuncSetAttribute(step_layer_kernel<false>,
                         cudaFuncAttributeMaxDynamicSharedMemorySize, SMEM_BYTES);
    cudaFuncSetAttribute(precompute_p0_kernel,
                         cudaFuncAttributeMaxDynamicSharedMemorySize, SMEM_BYTES);

    float *stA, *stB, *bp;
    __half *shA, *shB, *xh, *Wp;
    cudaGetSymbolAddress((void**)&stA, g_stA);
    cudaGetSymbolAddress((void**)&stB, g_stB);
    cudaGetSymbolAddress((void**)&shA, g_shA);
    cudaGetSymbolAddress((void**)&shB, g_shB);
    cudaGetSymbolAddress((void**)&xh,  g_xh);
    cudaGetSymbolAddress((void**)&Wp,  g_W);
    cudaGetSymbolAddress((void**)&bp,  g_bias);

    pack_w_kernel<<<4096, 256>>>(ws, wi, wt);
    pack_bias_kernel<<<32, 256>>>(bs, bi, bt);
    pack_x_kernel<<<2048, 256>>>(x);
    init_states_kernel<<<512, 256>>>();

    dim3 grid(NJC / 128, MM / 128);   // (16, 64)
    precompute_p0_kernel<<<grid, 256, SMEM_BYTES>>>(xh, Wp);

    for (int t = 0; t < MAXT; ++t) {
        float*  sinE  = (t & 1) ? stB : stA;
        float*  soutE = (t & 1) ? stA : stB;
        __half* sinH  = (t & 1) ? shB : shA;
        __half* soutH = (t & 1) ? shA : shB;
        const __half* curH = xh;
        for (int l = 0; l < NL; ++l) {
            if (l == 0)
                step_layer_kernel<true><<<grid, 256, SMEM_BYTES>>>(
                    curH,
                    sinH,
                    sinE,
                    soutE,
                    soutH,
                    Wp,
                    bp);
            else
                step_layer_kernel<false><<<grid, 256, SMEM_BYTES>>>(
                    curH,
                    sinH  + (size_t)l * MM * HD,
                    sinE  + (size_t)l * MM * HD,
                    soutE + (size_t)l * MM * HD,
                    soutH + (size_t)l * MM * HD,
                    Wp + (size_t)l * NJC * KK2,
                    bp + l * NJC);
            curH = soutH + (size_t)l * MM * HD;
        }
        conv_check_kernel<<<1, 1>>>(t);
    }
    finalize_kernel<<<2048, 256>>>((float*)d_out, out_size);
}

// round 15
// speedup vs baseline: 1.1366x; 1.0078x over previous
#include <cuda_runtime.h>
#include <cuda_fp16.h>
#include <cstdint>

// Problem constants
#define NL    4
#define HD    1024
#define KK2   2048
#define NJC   2048      // interleaved output cols (even=forcing, odd=tau)
#define MM    8192
#define MAXT  50
#define DTC   0.05f
#define EPS_TAU  1e-6f
#define EPS_CONV 1e-3f

#define STAGE_BYTES 32768          // A 16KB + B 16KB per stage (fp16, k-chunk 64)
#define SMEM_BYTES  (2 * STAGE_BYTES)

// step_layer MODE values
#define MODE_L0_FULL 0   // acc=P0, h-half GEMM (16 k-tiles, KOFF=HD)
#define MODE_FULL    1   // acc=0, full GEMM (32 k-tiles)
#define MODE_L0_T0   2   // acc=P0, no GEMM (h == 0 at t=0)
#define MODE_T0      3   // acc=0, cur-half only (16 k-tiles, KOFF=0; h == 0)

// ---------------- device scratch (static: no allocation allowed) ------------
__device__ __half g_W[(size_t)NL * NJC * KK2];   // packed fp16 weights [l][j][k]
__device__ float  g_bias[NL * NJC];              // interleaved biases
__device__ __half g_xh[(size_t)MM * HD];         // fp16 input x
__device__ float  g_stA[(size_t)NL * MM * HD];   // exact states ping
__device__ float  g_stB[(size_t)NL * MM * HD];   // exact states pong
__device__ __half g_shA[(size_t)NL * MM * HD];   // fp16 states ping
__device__ __half g_shB[(size_t)NL * MM * HD];   // fp16 states pong
// Layer-0 constant partial sums (x-half of the combined GEMM), fragment layout.
__device__ float  g_P0[(size_t)MM * NJC];
__device__ int      g_done;
__device__ int      g_tconv;
__device__ unsigned g_maxd;
__device__ int      g_tiles3;     // layer-3 tile completion counter (per step)

// ---------------- PTX helpers ----------------
__device__ __forceinline__ unsigned sptr(const void* p) {
    return (unsigned)__cvta_generic_to_shared(p);
}
__device__ __forceinline__ void cpasync16(unsigned dst, const void* src) {
    asm volatile("cp.async.cg.shared.global [%0], [%1], 16;\n" :: "r"(dst), "l"(src));
}
__device__ __forceinline__ void cpcommit() { asm volatile("cp.async.commit_group;\n"); }
template<int N> __device__ __forceinline__ void cpwait() {
    asm volatile("cp.async.wait_group %0;\n" :: "n"(N));
}
__device__ __forceinline__ void ldsm4(unsigned& r0, unsigned& r1, unsigned& r2, unsigned& r3,
                                      unsigned addr) {
    asm volatile("ldmatrix.sync.aligned.m8n8.x4.shared.b16 {%0,%1,%2,%3}, [%4];\n"
                 : "=r"(r0), "=r"(r1), "=r"(r2), "=r"(r3) : "r"(addr));
}
__device__ __forceinline__ void mma_f16(float* c, const unsigned* a, const unsigned* b) {
    asm volatile(
        "mma.sync.aligned.m16n8k16.row.col.f32.f16.f16.f32 "
        "{%0,%1,%2,%3}, {%4,%5,%6,%7}, {%8,%9}, {%0,%1,%2,%3};\n"
        : "+f"(c[0]), "+f"(c[1]), "+f"(c[2]), "+f"(c[3])
        : "r"(a[0]), "r"(a[1]), "r"(a[2]), "r"(a[3]), "r"(b[0]), "r"(b[1]));
}
// Accurate tanh independent of fast-math substitutions
__device__ __forceinline__ float my_tanh(float x) {
    float ax = fabsf(x);
    float e  = __expf(-2.0f * ax);
    float r  = (1.0f - e) / (1.0f + e);
    return copysignf(r, x);
}

// ---------------- pack / init kernels ----------------
__global__ void pack_w_kernel(const float* __restrict__ ws, const float* __restrict__ wi,
                              const float* __restrict__ wt) {
    const size_t total = (size_t)NL * NJC * KK2;
    for (size_t idx = (size_t)blockIdx.x * blockDim.x + threadIdx.x; idx < total;
         idx += (size_t)gridDim.x * blockDim.x) {
        int k = (int)(idx & (KK2 - 1));
        size_t r = idx >> 11;
        int j = (int)(r & (NJC - 1));
        int l = (int)(r >> 11);
        int n = j >> 1;
        float v;
        if (j & 1) v = wt[((size_t)(l * HD + n)) * (2 * HD) + k];
        else       v = (k < HD) ? wi[((size_t)(l * HD + n)) * HD + k]
                                : ws[((size_t)(l * HD + n)) * HD + (k - HD)];
        g_W[idx] = __float2half_rn(v);
    }
}

__global__ void pack_bias_kernel(const float* __restrict__ bs, const float* __restrict__ bi,
                                 const float* __restrict__ bt) {
    int idx = blockIdx.x * blockDim.x + threadIdx.x;
    if (idx < NL * NJC) {
        int j = idx & (NJC - 1);
        int l = idx >> 11;
        int n = j >> 1;
        g_bias[idx] = (j & 1) ? bt[l * HD + n] : (bs[l * HD + n] + bi[l * HD + n]);
    }
}

__global__ void pack_x_kernel(const float* __restrict__ x) {
    const size_t n = (size_t)MM * HD;
    for (size_t i = (size_t)blockIdx.x * blockDim.x + threadIdx.x; i < n;
         i += (size_t)gridDim.x * blockDim.x)
        g_xh[i] = __float2half_rn(x[i]);
}

__global__ void init_states_kernel() {
    const size_t n4 = ((size_t)NL * MM * HD) / 4;
    float4* pa = (float4*)g_stA;
    uint2*  ph = (uint2*)g_shA;
    float4 z = make_float4(0.f, 0.f, 0.f, 0.f);
    uint2  zh = make_uint2(0u, 0u);
    for (size_t i = (size_t)blockIdx.x * blockDim.x + threadIdx.x; i < n4;
         i += (size_t)gridDim.x * blockDim.x) { pa[i] = z; ph[i] = zh; }
    if (blockIdx.x == 0 && threadIdx.x == 0) {
        g_done = 0; g_tconv = MAXT; g_maxd = 0u; g_tiles3 = 0;
    }
}

// ---------------- shared GEMM mainloop (templated) ---------------------------
template<int NKT, int KOFF>
__device__ __forceinline__ void gemm_tiles(
    float acc[4][4][4], const __half* curH, const __half* hinH,
    const __half* W, int row0, int j0, unsigned smemB,
    int tid, int lane, int warpM, int warpJ) {
    const int qr = tid >> 3;
    const int qg = tid & 7;

    auto load_stage = [&](int kt, int st) {
        int kk = KOFF + kt * 64;
        const __half* abase = (kk < HD) ? (curH + kk) : (hinH + (kk - HD));
        const __half* bbase = W + kk;
        unsigned aS = smemB + (unsigned)st * STAGE_BYTES;
        unsigned bS = aS + 16384u;
        #pragma unroll
        for (int i = 0; i < 4; ++i) {
            int r = i * 32 + qr;
            unsigned sw = (unsigned)((r * 8 + (qg ^ (r & 7))) << 4);
            cpasync16(aS + sw, abase + (size_t)(row0 + r) * HD + qg * 8);
            cpasync16(bS + sw, bbase + (size_t)(j0 + r) * KK2 + qg * 8);
        }
    };

    load_stage(0, 0);
    cpcommit();

    for (int kt = 0; kt < NKT; ++kt) {
        if (kt + 1 < NKT) { load_stage(kt + 1, (kt + 1) & 1); cpcommit(); cpwait<1>(); }
        else              { cpwait<0>(); }
        __syncthreads();
        unsigned aB = smemB + (unsigned)(kt & 1) * STAGE_BYTES;
        unsigned bB = aB + 16384u;

        #pragma unroll
        for (int ks = 0; ks < 4; ++ks) {
            unsigned afr[4][4];
            #pragma unroll
            for (int mt = 0; mt < 4; ++mt) {
                int row = warpM * 64 + mt * 16 + ((lane >> 3) & 1) * 8 + (lane & 7);
                int grp = ks * 2 + ((lane >> 4) & 1);
                unsigned ad = aB + (unsigned)((row * 8 + (grp ^ (row & 7))) << 4);
                ldsm4(afr[mt][0], afr[mt][1], afr[mt][2], afr[mt][3], ad);
            }
            unsigned bfr[4][2];
            #pragma unroll
            for (int p = 0; p < 2; ++p) {
                int jrow = warpJ * 32 + p * 16 + ((lane >> 4) & 1) * 8 + (lane & 7);
                int grp  = ks * 2 + ((lane >> 3) & 1);
                unsigned ad = bB + (unsigned)((jrow * 8 + (grp ^ (jrow & 7))) << 4);
                ldsm4(bfr[p * 2][0], bfr[p * 2][1], bfr[p * 2 + 1][0], bfr[p * 2 + 1][1], ad);
            }
            #pragma unroll
            for (int mt = 0; mt < 4; ++mt)
                #pragma unroll
                for (int nt = 0; nt < 4; ++nt)
                    mma_f16(acc[mt][nt], afr[mt], bfr[nt]);
        }
        __syncthreads();
    }
}

// ---------------- layer-0 constant-part precompute ---------------------------
__global__ void __launch_bounds__(256, 2) precompute_p0_kernel(
    const __half* __restrict__ xh, const __half* __restrict__ W0) {
    const int tid   = threadIdx.x;
    const int lane  = tid & 31;
    const int wid   = tid >> 5;
    const int warpM = wid & 1;
    const int warpJ = wid >> 1;
    const int row0  = blockIdx.y * 128;
    const int j0    = blockIdx.x * 128;

    extern __shared__ char smem[];
    const unsigned smemB = sptr(smem);

    float acc[4][4][4];
    #pragma unroll
    for (int a = 0; a < 4; ++a)
        #pragma unroll
        for (int b = 0; b < 4; ++b)
            #pragma unroll
            for (int c = 0; c < 4; ++c) acc[a][b][c] = 0.f;

    gemm_tiles<16, 0>(acc, xh, xh, W0, row0, j0, smemB, tid, lane, warpM, warpJ);

    float4* blob = (float4*)g_P0 + (size_t)(blockIdx.y * 16 + blockIdx.x) * 4096;
    #pragma unroll
    for (int mt = 0; mt < 4; ++mt)
        #pragma unroll
        for (int nt = 0; nt < 4; ++nt)
            blob[(mt * 4 + nt) * 256 + tid] =
                make_float4(acc[mt][nt][0], acc[mt][nt][1], acc[mt][nt][2], acc[mt][nt][3]);
}

// ---------------- fused fp16-MMA GEMM + state-update kernel ------------------
// CHECK=true (layer 3): last-finishing CTA resolves convergence for step t.
template<int MODE, bool CHECK>
__global__ void __launch_bounds__(256, 2) step_layer_kernel(
    const __half* __restrict__ curH, const __half* __restrict__ hinH,
    const float* __restrict__ hinE, float* __restrict__ houtE,
    __half* __restrict__ houtH, const __half* __restrict__ W,
    const float* __restrict__ bias, int t) {
    const int tid   = threadIdx.x;
    const int lane  = tid & 31;
    const int wid   = tid >> 5;
    const int warpM = wid & 1;
    const int warpJ = wid >> 1;
    const int row0  = blockIdx.y * 128;
    const int j0    = blockIdx.x * 128;
    const int nb    = blockIdx.x * 64 + warpJ * 16;
    const int g8    = lane >> 2, tc = lane & 3;

    // Frozen after convergence: propagate exact states only.
    if (*(volatile int*)&g_done) {
        int r   = row0 + (tid >> 1);
        int nb2 = blockIdx.x * 64 + (tid & 1) * 32;
        const float4* s4 = (const float4*)(hinE  + (size_t)r * HD + nb2);
        float4*       d4 = (float4*)(houtE + (size_t)r * HD + nb2);
        #pragma unroll
        for (int i = 0; i < 8; ++i) d4[i] = s4[i];
        if (CHECK && tid == 0) {
            __threadfence();
            int c = atomicAdd(&g_tiles3, 1);
            if (c == 1023) { g_maxd = 0u; g_tiles3 = 0; __threadfence(); }
        }
        return;
    }

    // L2-prefetch the epilogue's exact-state tile.
    {
        const float* pp = hinE + (size_t)(row0 + (tid >> 1)) * HD
                               + blockIdx.x * 64 + (tid & 1) * 32;
        asm volatile("prefetch.global.L2 [%0];" :: "l"(pp));
    }

    extern __shared__ char smem[];
    const unsigned smemB = sptr(smem);

    float acc[4][4][4];
    if (MODE == MODE_L0_FULL || MODE == MODE_L0_T0) {
        const float4* blob = (const float4*)g_P0
                           + (size_t)(blockIdx.y * 16 + blockIdx.x) * 4096;
        #pragma unroll
        for (int mt = 0; mt < 4; ++mt)
            #pragma unroll
            for (int nt = 0; nt < 4; ++nt) {
                float4 v = blob[(mt * 4 + nt) * 256 + tid];
                acc[mt][nt][0] = v.x; acc[mt][nt][1] = v.y;
                acc[mt][nt][2] = v.z; acc[mt][nt][3] = v.w;
            }
    } else {
        #pragma unroll
        for (int a = 0; a < 4; ++a)
            #pragma unroll
            for (int b = 0; b < 4; ++b)
                #pragma unroll
                for (int c = 0; c < 4; ++c) acc[a][b][c] = 0.f;
    }

    if (MODE == MODE_L0_FULL)
        gemm_tiles<16, HD>(acc, curH, hinH, W, row0, j0, smemB, tid, lane, warpM, warpJ);
    else if (MODE == MODE_FULL)
        gemm_tiles<32, 0>(acc, curH, hinH, W, row0, j0, smemB, tid, lane, warpM, warpJ);
    else if (MODE == MODE_T0)
        gemm_tiles<16, 0>(acc, curH, hinH, W, row0, j0, smemB, tid, lane, warpM, warpJ);
    // MODE_L0_T0: no GEMM — h == 0 contributes exact +0.0

    // ---- epilogue: liquid-time state update on thread-local (f,tau) pairs ----
    float dmax = 0.f;
    const int rb = row0 + warpM * 64;
    #pragma unroll
    for (int mt = 0; mt < 4; ++mt) {
        #pragma unroll
        for (int nt = 0; nt < 4; ++nt) {
            int n = nb + nt * 4 + tc;
            float2 bb = ((const float2*)bias)[n];   // .x forcing, .y tau
            int r0r = rb + mt * 16 + g8;
            #pragma unroll
            for (int hh = 0; hh < 2; ++hh) {
                int r = r0r + hh * 8;
                float pf = acc[mt][nt][hh * 2 + 0] + bb.x;
                float pt = acc[mt][nt][hh * 2 + 1] + bb.y;
                float h   = hinE[(size_t)r * HD + n];
                float f   = my_tanh(pf);
                float tau = 0.5f * (my_tanh(0.5f * pt) + 1.0f);   // stable sigmoid
                float hn  = h + DTC * (f - h / (tau + EPS_TAU));
                hn = fminf(10.0f, fmaxf(-10.0f, hn));
                houtE[(size_t)r * HD + n] = hn;
                houtH[(size_t)r * HD + n] = __float2half_rn(hn);
                dmax = fmaxf(dmax, fabsf(hn - h));
            }
        }
    }

    #pragma unroll
    for (int o = 16; o > 0; o >>= 1)
        dmax = fmaxf(dmax, __shfl_xor_sync(0xffffffffu, dmax, o));
    float* sred = (float*)smem;
    if (lane == 0) sred[wid] = dmax;
    __syncthreads();
    if (tid == 0) {
        float m = sred[0];
        #pragma unroll
        for (int i = 1; i < 8; ++i) m = fmaxf(m, sred[i]);
        atomicMax(&g_maxd, __float_as_uint(m));
        if (CHECK) {
            __threadfence();                      // publish stores + maxd
            int c = atomicAdd(&g_tiles3, 1);
            if (c == 1023) {                      // last tile of step t: resolve
                __threadfence();
                unsigned md = atomicMax(&g_maxd, 0u);   // read-only max
                if (!g_done && __uint_as_float(md) < EPS_CONV) {
                    g_done = 1; g_tconv = t;
                }
                g_maxd = 0u;
                g_tiles3 = 0;
                __threadfence();
            }
        }
    }
}

__global__ void finalize_kernel(float* __restrict__ out, int out_size) {
    const float* src = g_stA + (size_t)3 * MM * HD;   // layer 3, final parity = A
    const size_t n = (size_t)MM * HD;
    for (size_t i = (size_t)blockIdx.x * blockDim.x + threadIdx.x; i < n;
         i += (size_t)gridDim.x * blockDim.x)
        out[i] = src[i];
    if (blockIdx.x == 0 && threadIdx.x == 0 && (size_t)out_size > n)
        out[n] = (float)g_tconv;
}

// ---------------- host orchestration (graph-capturable) ----------------------
extern "C" void kernel_launch(void* const* d_in, const int* in_sizes, int n_in,
                              void* d_out, int out_size) {
    const float* x  = (const float*)d_in[0];
    const float* ws = (const float*)d_in[1];
    const float* bs = (const float*)d_in[2];
    const float* wi = (const float*)d_in[3];
    const float* bi = (const float*)d_in[4];
    const float* wt = (const float*)d_in[5];
    const float* bt = (const float*)d_in[6];
    (void)in_sizes; (void)n_in;

    cudaFuncSetAttribute(step_layer_kernel<MODE_L0_FULL, false>,
                         cudaFuncAttributeMaxDynamicSharedMemorySize, SMEM_BYTES);
    cudaFuncSetAttribute(step_layer_kernel<MODE_FULL, false>,
                         cudaFuncAttributeMaxDynamicSharedMemorySize, SMEM_BYTES);
    cudaFuncSetAttribute(step_layer_kernel<MODE_FULL, true>,
                         cudaFuncAttributeMaxDynamicSharedMemorySize, SMEM_BYTES);
    cudaFuncSetAttribute(step_layer_kernel<MODE_L0_T0, false>,
                         cudaFuncAttributeMaxDynamicSharedMemorySize, SMEM_BYTES);
    cudaFuncSetAttribute(step_layer_kernel<MODE_T0, false>,
                         cudaFuncAttributeMaxDynamicSharedMemorySize, SMEM_BYTES);
    cudaFuncSetAttribute(step_layer_kernel<MODE_T0, true>,
                         cudaFuncAttributeMaxDynamicSharedMemorySize, SMEM_BYTES);
    cudaFuncSetAttribute(precompute_p0_kernel,
                         cudaFuncAttributeMaxDynamicSharedMemorySize, SMEM_BYTES);

    float *stA, *stB, *bp;
    __half *shA, *shB, *xh, *Wp;
    cudaGetSymbolAddress((void**)&stA, g_stA);
    cudaGetSymbolAddress((void**)&stB, g_stB);
    cudaGetSymbolAddress((void**)&shA, g_shA);
    cudaGetSymbolAddress((void**)&shB, g_shB);
    cudaGetSymbolAddress((void**)&xh,  g_xh);
    cudaGetSymbolAddress((void**)&Wp,  g_W);
    cudaGetSymbolAddress((void**)&bp,  g_bias);

    pack_w_kernel<<<4096, 256>>>(ws, wi, wt);
    pack_bias_kernel<<<32, 256>>>(bs, bi, bt);
    pack_x_kernel<<<2048, 256>>>(x);
    init_states_kernel<<<512, 256>>>();

    dim3 grid(NJC / 128, MM / 128);   // (16, 64)
    precompute_p0_kernel<<<grid, 256, SMEM_BYTES>>>(xh, Wp);

    for (int t = 0; t < MAXT; ++t) {
        float*  sinE  = (t & 1) ? stB : stA;
        float*  soutE = (t & 1) ? stA : stB;
        __half* sinH  = (t & 1) ? shB : shA;
        __half* soutH = (t & 1) ? shA : shB;
        const __half* curH = xh;
        for (int l = 0; l < NL; ++l) {
            const __half* hinH  = sinH  + (size_t)l * MM * HD;
            const float*  hinE  = sinE  + (size_t)l * MM * HD;
            float*        houtE = soutE + (size_t)l * MM * HD;
            __half*       houtH = soutH + (size_t)l * MM * HD;
            const __half* W     = Wp + (size_t)l * NJC * KK2;
            const float*  bias  = bp + l * NJC;
            if (t == 0) {
                if (l == 0)
                    step_layer_kernel<MODE_L0_T0, false><<<grid, 256, SMEM_BYTES>>>(
                        curH, hinH, hinE, houtE, houtH, W, bias, t);
                else if (l < 3)
                    step_layer_kernel<MODE_T0, false><<<grid, 256, SMEM_BYTES>>>(
                        curH, hinH, hinE, houtE, houtH, W, bias, t);
                else
                    step_layer_kernel<MODE_T0, true><<<grid, 256, SMEM_BYTES>>>(
                        curH, hinH, hinE, houtE, houtH, W, bias, t);
            } else {
                if (l == 0)
                    step_layer_kernel<MODE_L0_FULL, false><<<grid, 256, SMEM_BYTES>>>(
                        curH, hinH, hinE, houtE, houtH, W, bias, t);
                else if (l < 3)
                    step_layer_kernel<MODE_FULL, false><<<grid, 256, SMEM_BYTES>>>(
                        curH, hinH, hinE, houtE, houtH, W, bias, t);
                else
                    step_layer_kernel<MODE_FULL, true><<<grid, 256, SMEM_BYTES>>>(
                        curH, hinH, hinE, houtE, houtH, W, bias, t);
            }
            curH = houtH;
        }
    }
    finalize_kernel<<<2048, 256>>>((float*)d_out, out_size);
}

// round 17
// speedup vs baseline: 1.1611x; 1.0216x over previous
#include <cuda_runtime.h>
#include <cuda_fp16.h>
#include <cstdint>

// Problem constants
#define NL    4
#define HD    1024
#define KK2   2048
#define NJC   2048      // interleaved output cols (even=forcing, odd=tau)
#define MM    8192
#define MAXT  50
#define DTC   0.05f
#define EPS_TAU  1e-6f
#define EPS_CONV 1e-3f

#define STAGE_BYTES 32768          // A 16KB + B 16KB per stage (fp16, k-chunk 64)
#define SMEM_BYTES  (2 * STAGE_BYTES)

// step_layer MODE values
#define MODE_L0_FULL 0   // acc=P0, h-half GEMM (16 k-tiles, KOFF=HD)
#define MODE_FULL    1   // acc=0, full GEMM (32 k-tiles)
#define MODE_L0_T0   2   // acc=P0, no GEMM (h == 0 at t=0)
#define MODE_T0      3   // acc=0, cur-half only (16 k-tiles, KOFF=0; h == 0)

// ---------------- device scratch (static: no allocation allowed) ------------
__device__ __half g_W[(size_t)NL * NJC * KK2];   // packed fp16 weights [l][j][k]
__device__ float  g_bias[NL * NJC];              // interleaved biases
__device__ __half g_xh[(size_t)MM * HD];         // fp16 input x
__device__ float  g_stA[(size_t)NL * MM * HD];   // exact states ping
__device__ float  g_stB[(size_t)NL * MM * HD];   // exact states pong
__device__ __half g_shA[(size_t)NL * MM * HD];   // fp16 states ping
__device__ __half g_shB[(size_t)NL * MM * HD];   // fp16 states pong
// Layer-0 constant partial sums (x-half of the combined GEMM), fragment layout.
__device__ float  g_P0[(size_t)MM * NJC];
__device__ int      g_done;
__device__ int      g_tconv;
__device__ unsigned g_maxd;
__device__ int      g_tiles3;     // layer-3 tile completion counter (per step)

// ---------------- PTX helpers ----------------
__device__ __forceinline__ unsigned sptr(const void* p) {
    return (unsigned)__cvta_generic_to_shared(p);
}
__device__ __forceinline__ void cpasync16(unsigned dst, const void* src) {
    asm volatile("cp.async.cg.shared.global [%0], [%1], 16;\n" :: "r"(dst), "l"(src));
}
__device__ __forceinline__ void cpcommit() { asm volatile("cp.async.commit_group;\n"); }
template<int N> __device__ __forceinline__ void cpwait() {
    asm volatile("cp.async.wait_group %0;\n" :: "n"(N));
}
__device__ __forceinline__ void ldsm4(unsigned& r0, unsigned& r1, unsigned& r2, unsigned& r3,
                                      unsigned addr) {
    asm volatile("ldmatrix.sync.aligned.m8n8.x4.shared.b16 {%0,%1,%2,%3}, [%4];\n"
                 : "=r"(r0), "=r"(r1), "=r"(r2), "=r"(r3) : "r"(addr));
}
__device__ __forceinline__ void mma_f16(float* c, const unsigned* a, const unsigned* b) {
    asm volatile(
        "mma.sync.aligned.m16n8k16.row.col.f32.f16.f16.f32 "
        "{%0,%1,%2,%3}, {%4,%5,%6,%7}, {%8,%9}, {%0,%1,%2,%3};\n"
        : "+f"(c[0]), "+f"(c[1]), "+f"(c[2]), "+f"(c[3])
        : "r"(a[0]), "r"(a[1]), "r"(a[2]), "r"(a[3]), "r"(b[0]), "r"(b[1]));
}
// Accurate tanh via MUFU exp + fast divide (~2 ulp divide, |err| ~1e-7 abs)
__device__ __forceinline__ float my_tanh(float x) {
    float ax = fabsf(x);
    float e  = __expf(-2.0f * ax);
    float r  = __fdividef(1.0f - e, 1.0f + e);
    return copysignf(r, x);
}

// ---------------- pack / init kernels ----------------
__global__ void pack_w_kernel(const float* __restrict__ ws, const float* __restrict__ wi,
                              const float* __restrict__ wt) {
    const size_t total = (size_t)NL * NJC * KK2;
    for (size_t idx = (size_t)blockIdx.x * blockDim.x + threadIdx.x; idx < total;
         idx += (size_t)gridDim.x * blockDim.x) {
        int k = (int)(idx & (KK2 - 1));
        size_t r = idx >> 11;
        int j = (int)(r & (NJC - 1));
        int l = (int)(r >> 11);
        int n = j >> 1;
        float v;
        if (j & 1) v = wt[((size_t)(l * HD + n)) * (2 * HD) + k];
        else       v = (k < HD) ? wi[((size_t)(l * HD + n)) * HD + k]
                                : ws[((size_t)(l * HD + n)) * HD + (k - HD)];
        g_W[idx] = __float2half_rn(v);
    }
}

__global__ void pack_bias_kernel(const float* __restrict__ bs, const float* __restrict__ bi,
                                 const float* __restrict__ bt) {
    int idx = blockIdx.x * blockDim.x + threadIdx.x;
    if (idx < NL * NJC) {
        int j = idx & (NJC - 1);
        int l = idx >> 11;
        int n = j >> 1;
        g_bias[idx] = (j & 1) ? bt[l * HD + n] : (bs[l * HD + n] + bi[l * HD + n]);
    }
}

__global__ void pack_x_kernel(const float* __restrict__ x) {
    const size_t n = (size_t)MM * HD;
    for (size_t i = (size_t)blockIdx.x * blockDim.x + threadIdx.x; i < n;
         i += (size_t)gridDim.x * blockDim.x)
        g_xh[i] = __float2half_rn(x[i]);
}

__global__ void init_states_kernel() {
    const size_t n4 = ((size_t)NL * MM * HD) / 4;
    float4* pa = (float4*)g_stA;
    uint2*  ph = (uint2*)g_shA;
    float4 z = make_float4(0.f, 0.f, 0.f, 0.f);
    uint2  zh = make_uint2(0u, 0u);
    for (size_t i = (size_t)blockIdx.x * blockDim.x + threadIdx.x; i < n4;
         i += (size_t)gridDim.x * blockDim.x) { pa[i] = z; ph[i] = zh; }
    if (blockIdx.x == 0 && threadIdx.x == 0) {
        g_done = 0; g_tconv = MAXT; g_maxd = 0u; g_tiles3 = 0;
    }
}

// ---------------- shared GEMM mainloop (templated) ---------------------------
template<int NKT, int KOFF>
__device__ __forceinline__ void gemm_tiles(
    float acc[4][4][4], const __half* curH, const __half* hinH,
    const __half* W, int row0, int j0, unsigned smemB,
    int tid, int lane, int warpM, int warpJ) {
    const int qr = tid >> 3;
    const int qg = tid & 7;

    auto load_stage = [&](int kt, int st) {
        int kk = KOFF + kt * 64;
        const __half* abase = (kk < HD) ? (curH + kk) : (hinH + (kk - HD));
        const __half* bbase = W + kk;
        unsigned aS = smemB + (unsigned)st * STAGE_BYTES;
        unsigned bS = aS + 16384u;
        #pragma unroll
        for (int i = 0; i < 4; ++i) {
            int r = i * 32 + qr;
            unsigned sw = (unsigned)((r * 8 + (qg ^ (r & 7))) << 4);
            cpasync16(aS + sw, abase + (size_t)(row0 + r) * HD + qg * 8);
            cpasync16(bS + sw, bbase + (size_t)(j0 + r) * KK2 + qg * 8);
        }
    };

    load_stage(0, 0);
    cpcommit();

    for (int kt = 0; kt < NKT; ++kt) {
        if (kt + 1 < NKT) { load_stage(kt + 1, (kt + 1) & 1); cpcommit(); cpwait<1>(); }
        else              { cpwait<0>(); }
        __syncthreads();
        unsigned aB = smemB + (unsigned)(kt & 1) * STAGE_BYTES;
        unsigned bB = aB + 16384u;

        #pragma unroll
        for (int ks = 0; ks < 4; ++ks) {
            unsigned afr[4][4];
            #pragma unroll
            for (int mt = 0; mt < 4; ++mt) {
                int row = warpM * 64 + mt * 16 + ((lane >> 3) & 1) * 8 + (lane & 7);
                int grp = ks * 2 + ((lane >> 4) & 1);
                unsigned ad = aB + (unsigned)((row * 8 + (grp ^ (row & 7))) << 4);
                ldsm4(afr[mt][0], afr[mt][1], afr[mt][2], afr[mt][3], ad);
            }
            unsigned bfr[4][2];
            #pragma unroll
            for (int p = 0; p < 2; ++p) {
                int jrow = warpJ * 32 + p * 16 + ((lane >> 4) & 1) * 8 + (lane & 7);
                int grp  = ks * 2 + ((lane >> 3) & 1);
                unsigned ad = bB + (unsigned)((jrow * 8 + (grp ^ (jrow & 7))) << 4);
                ldsm4(bfr[p * 2][0], bfr[p * 2][1], bfr[p * 2 + 1][0], bfr[p * 2 + 1][1], ad);
            }
            #pragma unroll
            for (int mt = 0; mt < 4; ++mt)
                #pragma unroll
                for (int nt = 0; nt < 4; ++nt)
                    mma_f16(acc[mt][nt], afr[mt], bfr[nt]);
        }
        __syncthreads();
    }
}

// ---------------- layer-0 constant-part precompute ---------------------------
__global__ void __launch_bounds__(256, 2) precompute_p0_kernel(
    const __half* __restrict__ xh, const __half* __restrict__ W0) {
    const int tid   = threadIdx.x;
    const int lane  = tid & 31;
    const int wid   = tid >> 5;
    const int warpM = wid & 1;
    const int warpJ = wid >> 1;
    const int row0  = blockIdx.y * 128;
    const int j0    = blockIdx.x * 128;

    extern __shared__ char smem[];
    const unsigned smemB = sptr(smem);

    float acc[4][4][4];
    #pragma unroll
    for (int a = 0; a < 4; ++a)
        #pragma unroll
        for (int b = 0; b < 4; ++b)
            #pragma unroll
            for (int c = 0; c < 4; ++c) acc[a][b][c] = 0.f;

    gemm_tiles<16, 0>(acc, xh, xh, W0, row0, j0, smemB, tid, lane, warpM, warpJ);

    float4* blob = (float4*)g_P0 + (size_t)(blockIdx.y * 16 + blockIdx.x) * 4096;
    #pragma unroll
    for (int mt = 0; mt < 4; ++mt)
        #pragma unroll
        for (int nt = 0; nt < 4; ++nt)
            blob[(mt * 4 + nt) * 256 + tid] =
                make_float4(acc[mt][nt][0], acc[mt][nt][1], acc[mt][nt][2], acc[mt][nt][3]);
}

// ---------------- fused fp16-MMA GEMM + state-update kernel ------------------
// CHECK=true (layer 3): last-finishing CTA resolves convergence for step t.
template<int MODE, bool CHECK>
__global__ void __launch_bounds__(256, 2) step_layer_kernel(
    const __half* __restrict__ curH, const __half* __restrict__ hinH,
    const float* __restrict__ hinE, float* __restrict__ houtE,
    __half* __restrict__ houtH, const __half* __restrict__ W,
    const float* __restrict__ bias, int t) {
    const int tid   = threadIdx.x;
    const int lane  = tid & 31;
    const int wid   = tid >> 5;
    const int warpM = wid & 1;
    const int warpJ = wid >> 1;
    const int row0  = blockIdx.y * 128;
    const int j0    = blockIdx.x * 128;
    const int nb    = blockIdx.x * 64 + warpJ * 16;
    const int g8    = lane >> 2, tc = lane & 3;

    // Frozen after convergence: propagate exact states only.
    if (*(volatile int*)&g_done) {
        int r   = row0 + (tid >> 1);
        int nb2 = blockIdx.x * 64 + (tid & 1) * 32;
        const float4* s4 = (const float4*)(hinE  + (size_t)r * HD + nb2);
        float4*       d4 = (float4*)(houtE + (size_t)r * HD + nb2);
        #pragma unroll
        for (int i = 0; i < 8; ++i) d4[i] = s4[i];
        if (CHECK && tid == 0) {
            __threadfence();
            int c = atomicAdd(&g_tiles3, 1);
            if (c == 1023) { g_maxd = 0u; g_tiles3 = 0; __threadfence(); }
        }
        return;
    }

    // L2-prefetch the epilogue's exact-state tile.
    {
        const float* pp = hinE + (size_t)(row0 + (tid >> 1)) * HD
                               + blockIdx.x * 64 + (tid & 1) * 32;
        asm volatile("prefetch.global.L2 [%0];" :: "l"(pp));
    }

    extern __shared__ char smem[];
    const unsigned smemB = sptr(smem);

    float acc[4][4][4];
    if (MODE == MODE_L0_FULL || MODE == MODE_L0_T0) {
        const float4* blob = (const float4*)g_P0
                           + (size_t)(blockIdx.y * 16 + blockIdx.x) * 4096;
        #pragma unroll
        for (int mt = 0; mt < 4; ++mt)
            #pragma unroll
            for (int nt = 0; nt < 4; ++nt) {
                float4 v = blob[(mt * 4 + nt) * 256 + tid];
                acc[mt][nt][0] = v.x; acc[mt][nt][1] = v.y;
                acc[mt][nt][2] = v.z; acc[mt][nt][3] = v.w;
            }
    } else {
        #pragma unroll
        for (int a = 0; a < 4; ++a)
            #pragma unroll
            for (int b = 0; b < 4; ++b)
                #pragma unroll
                for (int c = 0; c < 4; ++c) acc[a][b][c] = 0.f;
    }

    if (MODE == MODE_L0_FULL)
        gemm_tiles<16, HD>(acc, curH, hinH, W, row0, j0, smemB, tid, lane, warpM, warpJ);
    else if (MODE == MODE_FULL)
        gemm_tiles<32, 0>(acc, curH, hinH, W, row0, j0, smemB, tid, lane, warpM, warpJ);
    else if (MODE == MODE_T0)
        gemm_tiles<16, 0>(acc, curH, hinH, W, row0, j0, smemB, tid, lane, warpM, warpJ);
    // MODE_L0_T0: no GEMM — h == 0 contributes exact +0.0

    // ---- epilogue: liquid-time state update on thread-local (f,tau) pairs ----
    float dmax = 0.f;
    const int rb = row0 + warpM * 64;
    #pragma unroll
    for (int mt = 0; mt < 4; ++mt) {
        #pragma unroll
        for (int nt = 0; nt < 4; ++nt) {
            int n = nb + nt * 4 + tc;
            float2 bb = ((const float2*)bias)[n];   // .x forcing, .y tau
            int r0r = rb + mt * 16 + g8;
            #pragma unroll
            for (int hh = 0; hh < 2; ++hh) {
                int r = r0r + hh * 8;
                float pf = acc[mt][nt][hh * 2 + 0] + bb.x;
                float pt = acc[mt][nt][hh * 2 + 1] + bb.y;
                float h   = hinE[(size_t)r * HD + n];
                float f   = my_tanh(pf);
                float tau = 0.5f * (my_tanh(0.5f * pt) + 1.0f);   // stable sigmoid
                float hn  = h + DTC * (f - __fdividef(h, tau + EPS_TAU));
                hn = fminf(10.0f, fmaxf(-10.0f, hn));
                houtE[(size_t)r * HD + n] = hn;
                houtH[(size_t)r * HD + n] = __float2half_rn(hn);
                dmax = fmaxf(dmax, fabsf(hn - h));
            }
        }
    }

    #pragma unroll
    for (int o = 16; o > 0; o >>= 1)
        dmax = fmaxf(dmax, __shfl_xor_sync(0xffffffffu, dmax, o));
    float* sred = (float*)smem;
    if (lane == 0) sred[wid] = dmax;
    __syncthreads();
    if (tid == 0) {
        float m = sred[0];
        #pragma unroll
        for (int i = 1; i < 8; ++i) m = fmaxf(m, sred[i]);
        atomicMax(&g_maxd, __float_as_uint(m));
        if (CHECK) {
            __threadfence();                      // publish stores + maxd
            int c = atomicAdd(&g_tiles3, 1);
            if (c == 1023) {                      // last tile of step t: resolve
                __threadfence();
                unsigned md = atomicMax(&g_maxd, 0u);   // read-only max
                if (!g_done && __uint_as_float(md) < EPS_CONV) {
                    g_done = 1; g_tconv = t;
                }
                g_maxd = 0u;
                g_tiles3 = 0;
                __threadfence();
            }
        }
    }
}

__global__ void finalize_kernel(float* __restrict__ out, int out_size) {
    const float* src = g_stA + (size_t)3 * MM * HD;   // layer 3, final parity = A
    const size_t n = (size_t)MM * HD;
    for (size_t i = (size_t)blockIdx.x * blockDim.x + threadIdx.x; i < n;
         i += (size_t)gridDim.x * blockDim.x)
        out[i] = src[i];
    if (blockIdx.x == 0 && threadIdx.x == 0 && (size_t)out_size > n)
        out[n] = (float)g_tconv;
}

// ---------------- host orchestration (graph-capturable) ----------------------
extern "C" void kernel_launch(void* const* d_in, const int* in_sizes, int n_in,
                              void* d_out, int out_size) {
    const float* x  = (const float*)d_in[0];
    const float* ws = (const float*)d_in[1];
    const float* bs = (const float*)d_in[2];
    const float* wi = (const float*)d_in[3];
    const float* bi = (const float*)d_in[4];
    const float* wt = (const float*)d_in[5];
    const float* bt = (const float*)d_in[6];
    (void)in_sizes; (void)n_in;

    cudaFuncSetAttribute(step_layer_kernel<MODE_L0_FULL, false>,
                         cudaFuncAttributeMaxDynamicSharedMemorySize, SMEM_BYTES);
    cudaFuncSetAttribute(step_layer_kernel<MODE_FULL, false>,
                         cudaFuncAttributeMaxDynamicSharedMemorySize, SMEM_BYTES);
    cudaFuncSetAttribute(step_layer_kernel<MODE_FULL, true>,
                         cudaFuncAttributeMaxDynamicSharedMemorySize, SMEM_BYTES);
    cudaFuncSetAttribute(step_layer_kernel<MODE_L0_T0, false>,
                         cudaFuncAttributeMaxDynamicSharedMemorySize, SMEM_BYTES);
    cudaFuncSetAttribute(step_layer_kernel<MODE_T0, false>,
                         cudaFuncAttributeMaxDynamicSharedMemorySize, SMEM_BYTES);
    cudaFuncSetAttribute(step_layer_kernel<MODE_T0, true>,
                         cudaFuncAttributeMaxDynamicSharedMemorySize, SMEM_BYTES);
    cudaFuncSetAttribute(precompute_p0_kernel,
                         cudaFuncAttributeMaxDynamicSharedMemorySize, SMEM_BYTES);

    float *stA, *stB, *bp;
    __half *shA, *shB, *xh, *Wp;
    cudaGetSymbolAddress((void**)&stA, g_stA);
    cudaGetSymbolAddress((void**)&stB, g_stB);
    cudaGetSymbolAddress((void**)&shA, g_shA);
    cudaGetSymbolAddress((void**)&shB, g_shB);
    cudaGetSymbolAddress((void**)&xh,  g_xh);
    cudaGetSymbolAddress((void**)&Wp,  g_W);
    cudaGetSymbolAddress((void**)&bp,  g_bias);

    pack_w_kernel<<<4096, 256>>>(ws, wi, wt);
    pack_bias_kernel<<<32, 256>>>(bs, bi, bt);
    pack_x_kernel<<<2048, 256>>>(x);
    init_states_kernel<<<512, 256>>>();

    dim3 grid(NJC / 128, MM / 128);   // (16, 64)
    precompute_p0_kernel<<<grid, 256, SMEM_BYTES>>>(xh, Wp);

    for (int t = 0; t < MAXT; ++t) {
        float*  sinE  = (t & 1) ? stB : stA;
        float*  soutE = (t & 1) ? stA : stB;
        __half* sinH  = (t & 1) ? shB : shA;
        __half* soutH = (t & 1) ? shA : shB;
        const __half* curH = xh;
        for (int l = 0; l < NL; ++l) {
            const __half* hinH  = sinH  + (size_t)l * MM * HD;
            const float*  hinE  = sinE  + (size_t)l * MM * HD;
            float*        houtE = soutE + (size_t)l * MM * HD;
            __half*       houtH = soutH + (size_t)l * MM * HD;
            const __half* W     = Wp + (size_t)l * NJC * KK2;
            const float*  bias  = bp + l * NJC;
            if (t == 0) {
                if (l == 0)
                    step_layer_kernel<MODE_L0_T0, false><<<grid, 256, SMEM_BYTES>>>(
                        curH, hinH, hinE, houtE, houtH, W, bias, t);
                else if (l < 3)
                    step_layer_kernel<MODE_T0, false><<<grid, 256, SMEM_BYTES>>>(
                        curH, hinH, hinE, houtE, houtH, W, bias, t);
                else
                    step_layer_kernel<MODE_T0, true><<<grid, 256, SMEM_BYTES>>>(
                        curH, hinH, hinE, houtE, houtH, W, bias, t);
            } else {
                if (l == 0)
                    step_layer_kernel<MODE_L0_FULL, false><<<grid, 256, SMEM_BYTES>>>(
                        curH, hinH, hinE, houtE, houtH, W, bias, t);
                else if (l < 3)
                    step_layer_kernel<MODE_FULL, false><<<grid, 256, SMEM_BYTES>>>(
                        curH, hinH, hinE, houtE, houtH, W, bias, t);
                else
                    step_layer_kernel<MODE_FULL, true><<<grid, 256, SMEM_BYTES>>>(
                        curH, hinH, hinE, houtE, houtH, W, bias, t);
            }
            curH = houtH;
        }
    }
    finalize_kernel<<<2048, 256>>>((float*)d_out, out_size);
}